// round 15
// baseline (speedup 1.0000x reference)
#include <cuda_runtime.h>
#include <cuda_fp16.h>
#include <math.h>
#include <stdint.h>

#define BB   256
#define TT   256
#define DD   384
#define HH   64
#define MTOT (BB*TT)                       // 65536 rows
#define HEADELEMS ((size_t)MTOT*HH)

// scratch: q,k,v fp16 (attn operands) + transposed fp16 weights (proj)
__device__ __half g_h[3 * (size_t)MTOT * HH];
__device__ __half g_wh[192 * 384];

// ---------------------------------------------------------------------------
__device__ __forceinline__ uint32_t smem_u32(const void* p) {
    uint32_t a;
    asm("{ .reg .u64 t; cvta.to.shared.u64 t, %1; cvt.u32.u64 %0, t; }"
        : "=r"(a) : "l"(p));
    return a;
}

__device__ __forceinline__ void ldsm4(uint32_t r[4], uint32_t addr) {
    asm volatile("ldmatrix.sync.aligned.m8n8.x4.shared.b16 {%0,%1,%2,%3}, [%4];"
                 : "=r"(r[0]), "=r"(r[1]), "=r"(r[2]), "=r"(r[3]) : "r"(addr));
}

__device__ __forceinline__ void ldsm4t(uint32_t r[4], uint32_t addr) {
    asm volatile("ldmatrix.sync.aligned.m8n8.x4.trans.shared.b16 {%0,%1,%2,%3}, [%4];"
                 : "=r"(r[0]), "=r"(r[1]), "=r"(r[2]), "=r"(r[3]) : "r"(addr));
}

// fp16 mma
__device__ __forceinline__ void mma16816h(float c[4], const uint32_t a[4],
                                          uint32_t b0, uint32_t b1) {
    asm volatile(
        "mma.sync.aligned.m16n8k16.row.col.f32.f16.f16.f32 "
        "{%0,%1,%2,%3}, {%4,%5,%6,%7}, {%8,%9}, {%0,%1,%2,%3};"
        : "+f"(c[0]), "+f"(c[1]), "+f"(c[2]), "+f"(c[3])
        : "r"(a[0]), "r"(a[1]), "r"(a[2]), "r"(a[3]), "r"(b0), "r"(b1));
}

// pack two f32 -> f16x2 (first arg in low half)
__device__ __forceinline__ uint32_t packhf(float lo, float hi) {
    __half2 h = __floats2half2_rn(lo, hi);
    return *(uint32_t*)&h;
}

__device__ __forceinline__ void cpasync16(uint32_t dst, const void* src) {
    asm volatile("cp.async.cg.shared.global [%0], [%1], 16;"
                 :: "r"(dst), "l"(src));
}

// ---------------------------------------------------------------------------
// Weight prep: smem-tiled transpose, single fp16.
// ---------------------------------------------------------------------------
__global__ void wsplit_kernel(const float* __restrict__ Wq,
                              const float* __restrict__ Wk,
                              const float* __restrict__ Wv) {
    __shared__ float ws[32][65];
    const int sel = blockIdx.x / 12;
    const int k0  = (blockIdx.x % 12) * 32;
    const float* W = (sel == 0) ? Wq : (sel == 1) ? Wk : Wv;
    const int tid = threadIdx.x;

    #pragma unroll
    for (int it = 0; it < 8; ++it) {
        int idx = tid + it * 256;          // 0..2047
        int k = idx >> 6, n = idx & 63;
        ws[k][n] = W[(size_t)(k0 + k) * HH + n];
    }
    __syncthreads();
    #pragma unroll
    for (int it = 0; it < 8; ++it) {
        int idx = tid + it * 256;
        int n = idx >> 5, k = idx & 31;
        g_wh[(size_t)(sel * 64 + n) * DD + k0 + k] = __float2half_rn(ws[k][n]);
    }
}

// ---------------------------------------------------------------------------
// Pipelined fp16 single-product projection, KC=64 (6 chunks, half the syncs).
// A: fp32 x -> LDG -> fp16 -> STS, stride 72 halves, double buf.
// B: cp.async fp16 from g_wh, stride 72 halves, double buf.
// ---------------------------------------------------------------------------
#define KC    64
#define KS    72
#define ABUFH 4608     // halves: 64*72 per stage (x2)
#define B_BASE 9216
#define BBUFH 13824    // halves: 192*72 per stage (x2)
#define PROJ_SMEM ((9216 + 27648) * 2)   // 73728 bytes

__global__ void __launch_bounds__(256, 2) proj_mma_kernel(const float* __restrict__ x)
{
    extern __shared__ __half sm[];
    const uint32_t sb = smem_u32(sm);
    const int tid  = threadIdx.x;
    const int lane = tid & 31;
    const int wid  = tid >> 5;
    const int wm   = wid & 1;
    const int wn   = wid >> 1;
    const int m0   = blockIdx.x * 64;

    const int aRow = (lane & 7) + ((lane >> 3) & 1) * 8;
    const int aCol = ((lane >> 4) & 1) * 8;
    const int bN   = (lane & 7) + ((lane >> 4) & 1) * 8;
    const int bK   = ((lane >> 3) & 1) * 8;

    float c[2][6][4];
    #pragma unroll
    for (int mt = 0; mt < 2; ++mt)
        #pragma unroll
        for (int nt = 0; nt < 6; ++nt)
            #pragma unroll
            for (int j = 0; j < 4; ++j) c[mt][nt][j] = 0.f;

    float4 aCur[4], aNxt[4];

    // ---- prologue: B(0) cp.async -> stage0, A(0) -> regs
    {
        #pragma unroll
        for (int it = 0; it < 6; ++it) {
            int idx = tid + it * 256;              // 0..1535
            int n   = idx >> 3;                    // 0..191
            int kg  = (idx & 7) * 8;               // 0..56
            cpasync16(sb + (uint32_t)(B_BASE + n * KS + kg) * 2,
                      g_wh + (size_t)n * DD + kg);
        }
        asm volatile("cp.async.commit_group;" ::: "memory");
        #pragma unroll
        for (int it = 0; it < 4; ++it) {
            int idx = tid + it * 256;              // 0..1023 float4s
            int r = idx >> 4, c4 = (idx & 15) * 4;
            aCur[it] = *(const float4*)(x + (size_t)(m0 + r) * DD + c4);
        }
    }

    #pragma unroll 1
    for (int ch = 0; ch < 6; ++ch) {
        // ---- STS A(ch) (convert fp32 -> fp16)
        #pragma unroll
        for (int it = 0; it < 4; ++it) {
            int idx = tid + it * 256;
            int r = idx >> 4, c4 = (idx & 15) * 4;
            float4 v = aCur[it];
            int off = (ch & 1) * ABUFH + r * KS + c4;
            *(uint2*)(sm + off) = make_uint2(packhf(v.x, v.y), packhf(v.z, v.w));
        }

        // ---- drain B(ch), barrier
        asm volatile("cp.async.wait_group 0;" ::: "memory");
        __syncthreads();

        // ---- issue B(ch+1) + LDG A(ch+1); overlaps the MMA phase below
        if (ch < 5) {
            const int k1 = (ch + 1) * KC;
            #pragma unroll
            for (int it = 0; it < 6; ++it) {
                int idx = tid + it * 256;
                int n   = idx >> 3;
                int kg  = (idx & 7) * 8;
                cpasync16(sb + (uint32_t)(B_BASE + ((ch + 1) & 1) * BBUFH +
                                          n * KS + kg) * 2,
                          g_wh + (size_t)n * DD + k1 + kg);
            }
            asm volatile("cp.async.commit_group;" ::: "memory");
            #pragma unroll
            for (int it = 0; it < 4; ++it) {
                int idx = tid + it * 256;
                int r = idx >> 4, c4 = (idx & 15) * 4;
                aNxt[it] = *(const float4*)(x + (size_t)(m0 + r) * DD + k1 + c4);
            }
        }

        // ---- MMA over stage buffers: 4 k-sub-steps of 16
        const uint32_t aBase = (uint32_t)((ch & 1) * ABUFH);
        const uint32_t bBase = (uint32_t)(B_BASE + (ch & 1) * BBUFH);
        #pragma unroll
        for (int ks = 0; ks < 4; ++ks) {
            const int kk = ks * 16;
            uint32_t ah[2][4];
            #pragma unroll
            for (int mt = 0; mt < 2; ++mt) {
                uint32_t off = (uint32_t)((wm * 32 + mt * 16 + aRow) * KS + kk + aCol);
                ldsm4(ah[mt], sb + (aBase + off) * 2);
            }
            #pragma unroll
            for (int np = 0; np < 3; ++np) {
                uint32_t boff = (uint32_t)((wn * 48 + np * 16 + bN) * KS + kk + bK);
                uint32_t bh[4];
                ldsm4(bh, sb + (bBase + boff) * 2);
                #pragma unroll
                for (int mt = 0; mt < 2; ++mt)
                    #pragma unroll
                    for (int sub = 0; sub < 2; ++sub)
                        mma16816h(c[mt][sub + np * 2], ah[mt],
                                  bh[sub * 2], bh[sub * 2 + 1]);
            }
        }

        #pragma unroll
        for (int it = 0; it < 4; ++it) aCur[it] = aNxt[it];
    }

    // ---- epilogue: fp32 acc -> single fp16 to g_h (q pre-scaled by 0.125)
    const int t4 = lane >> 2;
    const int c2 = (lane & 3) * 2;
    #pragma unroll
    for (int mt = 0; mt < 2; ++mt)
        #pragma unroll
        for (int nt = 0; nt < 6; ++nt) {
            int col = wn * 48 + nt * 8 + c2;
            int sel = col >> 6;
            int hc  = col & 63;
            float s = (sel == 0) ? 0.125f : 1.0f;
            size_t base = (size_t)sel * HEADELEMS +
                          (size_t)(m0 + wm * 32 + mt * 16 + t4) * HH + hc;
            *(uint32_t*)(g_h + base) =
                packhf(c[mt][nt][0] * s, c[mt][nt][1] * s);
            *(uint32_t*)(g_h + base + 8 * HH) =
                packhf(c[mt][nt][2] * s, c[mt][nt][3] * s);
        }
}

// ---------------------------------------------------------------------------
// Tensor-core flash attention, fp16 single-product GEMMs, 2 CTAs/SM.
// (unchanged from R12)
// ---------------------------------------------------------------------------
#define AST 72
#define Q_S 0
#define K_S (256*AST)
#define V_S (2*256*AST)
#define ATTN_SMEM (3*256*AST*2)    // 110592 bytes

__global__ void __launch_bounds__(256, 2) attn_mma_kernel(float* __restrict__ out)
{
    extern __shared__ __half asmem[];
    const uint32_t sb = smem_u32(asmem);
    const int b    = blockIdx.x;
    const int tid  = threadIdx.x;
    const int lane = tid & 31;
    const int w    = tid >> 5;
    const int t4   = lane >> 2;
    const int tg   = lane & 3;

    // ---- cp.async load: 3 arrays of [256][64] fp16 -> stride-72 smem
    #pragma unroll
    for (int it = 0; it < 24; ++it) {
        const int arr = it >> 3;               // 8 iterations per array
        int rem = (tid + it * 256) - arr * 2048;
        int r   = rem >> 3;
        int kg  = (rem & 7) * 8;
        const __half* src = g_h + (size_t)arr * HEADELEMS +
                            ((size_t)b * TT + r) * HH + kg;
        uint32_t dst = sb + (uint32_t)(arr * 256 * AST + r * AST + kg) * 2;
        cpasync16(dst, src);
    }
    asm volatile("cp.async.commit_group;\n\tcp.async.wait_group 0;" ::: "memory");
    __syncthreads();

    const int Rb[2] = { 16 * w, 240 - 16 * w };

    float o[2][8][4];
    float mrow[2][2], lrow[2][2];
    #pragma unroll
    for (int mt = 0; mt < 2; ++mt) {
        mrow[mt][0] = mrow[mt][1] = -1e30f;
        lrow[mt][0] = lrow[mt][1] = 0.f;
        #pragma unroll
        for (int nt = 0; nt < 8; ++nt)
            #pragma unroll
            for (int j = 0; j < 4; ++j) o[mt][nt][j] = 0.f;
    }

    const int qRow = lane & 15;
    const int qCol = ((lane >> 4) & 1) * 8;
    const int kRow = (lane & 7) + ((lane >> 4) & 1) * 8;
    const int kCol = ((lane >> 3) & 1) * 8;
    const int vRow = lane & 15;
    const int vCol = ((lane >> 4) & 1) * 8;

    #pragma unroll 1
    for (int s0 = 0; s0 < TT; s0 += 64) {
        #pragma unroll
        for (int mt = 0; mt < 2; ++mt) {
            const int base = Rb[mt];
            if (s0 > base + 15) continue;

            const int npMax = min(4, ((base + 15 - s0) >> 4) + 1);

            // ---- S = Q K^T (fp16, single product)
            float sc[8][4];
            #pragma unroll
            for (int nt = 0; nt < 8; ++nt)
                #pragma unroll
                for (int j = 0; j < 4; ++j) sc[nt][j] = 0.f;

            #pragma unroll
            for (int kc = 0; kc < 4; ++kc) {
                uint32_t qh[4];
                uint32_t qoff = (uint32_t)((base + qRow) * AST + kc * 16 + qCol);
                ldsm4(qh, sb + (Q_S + qoff) * 2);
                #pragma unroll
                for (int np = 0; np < 4; ++np) {
                    if (np < npMax) {
                        uint32_t koff = (uint32_t)((s0 + np * 16 + kRow) * AST + kc * 16 + kCol);
                        uint32_t kh[4];
                        ldsm4(kh, sb + (K_S + koff) * 2);
                        mma16816h(sc[2 * np],     qh, kh[0], kh[1]);
                        mma16816h(sc[2 * np + 1], qh, kh[2], kh[3]);
                    }
                }
            }

            // ---- causal mask + online softmax
            const int r0 = base + t4;
            const int r1 = r0 + 8;
            #pragma unroll
            for (int nt = 0; nt < 8; ++nt) {
                int col = s0 + 8 * nt + 2 * tg;
                if (col     > r0) sc[nt][0] = -1e30f;
                if (col + 1 > r0) sc[nt][1] = -1e30f;
                if (col     > r1) sc[nt][2] = -1e30f;
                if (col + 1 > r1) sc[nt][3] = -1e30f;
            }
            float mx0 = sc[0][0], mx1 = sc[0][2];
            #pragma unroll
            for (int nt = 0; nt < 8; ++nt) {
                mx0 = fmaxf(mx0, fmaxf(sc[nt][0], sc[nt][1]));
                mx1 = fmaxf(mx1, fmaxf(sc[nt][2], sc[nt][3]));
            }
            mx0 = fmaxf(mx0, __shfl_xor_sync(0xffffffffu, mx0, 1));
            mx0 = fmaxf(mx0, __shfl_xor_sync(0xffffffffu, mx0, 2));
            mx1 = fmaxf(mx1, __shfl_xor_sync(0xffffffffu, mx1, 1));
            mx1 = fmaxf(mx1, __shfl_xor_sync(0xffffffffu, mx1, 2));

            float nm0 = fmaxf(mrow[mt][0], mx0);
            float nm1 = fmaxf(mrow[mt][1], mx1);
            float corr0 = __expf(mrow[mt][0] - nm0);
            float corr1 = __expf(mrow[mt][1] - nm1);
            mrow[mt][0] = nm0;
            mrow[mt][1] = nm1;

            float sum0 = 0.f, sum1 = 0.f;
            #pragma unroll
            for (int nt = 0; nt < 8; ++nt) {
                sc[nt][0] = __expf(sc[nt][0] - nm0);
                sc[nt][1] = __expf(sc[nt][1] - nm0);
                sc[nt][2] = __expf(sc[nt][2] - nm1);
                sc[nt][3] = __expf(sc[nt][3] - nm1);
                sum0 += sc[nt][0] + sc[nt][1];
                sum1 += sc[nt][2] + sc[nt][3];
            }
            sum0 += __shfl_xor_sync(0xffffffffu, sum0, 1);
            sum0 += __shfl_xor_sync(0xffffffffu, sum0, 2);
            sum1 += __shfl_xor_sync(0xffffffffu, sum1, 1);
            sum1 += __shfl_xor_sync(0xffffffffu, sum1, 2);
            lrow[mt][0] = lrow[mt][0] * corr0 + sum0;
            lrow[mt][1] = lrow[mt][1] * corr1 + sum1;

            #pragma unroll
            for (int nt = 0; nt < 8; ++nt) {
                o[mt][nt][0] *= corr0;
                o[mt][nt][1] *= corr0;
                o[mt][nt][2] *= corr1;
                o[mt][nt][3] *= corr1;
            }

            // ---- O += P V (fp16, single product); skip zero tiles
            #pragma unroll
            for (int kv = 0; kv < 4; ++kv) {
                if (kv < npMax) {
                    uint32_t ph[4];
                    #pragma unroll
                    for (int half = 0; half < 2; ++half) {
                        const float* f = sc[2 * kv + half];
                        ph[2 * half]     = packhf(f[0], f[1]);
                        ph[2 * half + 1] = packhf(f[2], f[3]);
                    }
                    #pragma unroll
                    for (int np = 0; np < 4; ++np) {
                        uint32_t voff = (uint32_t)((s0 + kv * 16 + vRow) * AST + np * 16 + vCol);
                        uint32_t vh[4];
                        ldsm4t(vh, sb + (V_S + voff) * 2);
                        mma16816h(o[mt][2 * np],     ph, vh[0], vh[1]);
                        mma16816h(o[mt][2 * np + 1], ph, vh[2], vh[3]);
                    }
                }
            }
        }
    }

    // ---- write out
    #pragma unroll
    for (int mt = 0; mt < 2; ++mt) {
        const int r0 = Rb[mt] + t4;
        const float inv0 = 1.f / lrow[mt][0];
        const float inv1 = 1.f / lrow[mt][1];
        #pragma unroll
        for (int nt = 0; nt < 8; ++nt) {
            int col = 8 * nt + 2 * tg;
            size_t o0 = ((size_t)b * TT + r0) * HH + col;
            *(float2*)(out + o0)           = make_float2(o[mt][nt][0] * inv0,
                                                         o[mt][nt][1] * inv0);
            *(float2*)(out + o0 + 8 * HH)  = make_float2(o[mt][nt][2] * inv1,
                                                         o[mt][nt][3] * inv1);
        }
    }
}

// ---------------------------------------------------------------------------
extern "C" void kernel_launch(void* const* d_in, const int* in_sizes, int n_in,
                              void* d_out, int out_size)
{
    const float* x  = (const float*)d_in[0];
    const float* Wq = (const float*)d_in[1];
    const float* Wk = (const float*)d_in[2];
    const float* Wv = (const float*)d_in[3];
    float* out = (float*)d_out;

    cudaFuncSetAttribute(proj_mma_kernel,
                         cudaFuncAttributeMaxDynamicSharedMemorySize, PROJ_SMEM);
    cudaFuncSetAttribute(attn_mma_kernel,
                         cudaFuncAttributeMaxDynamicSharedMemorySize, ATTN_SMEM);

    wsplit_kernel<<<36, 256>>>(Wq, Wk, Wv);
    proj_mma_kernel<<<MTOT / 64, 256, PROJ_SMEM>>>(x);
    attn_mma_kernel<<<BB, 256, ATTN_SMEM>>>(out);
}

// round 16
// speedup vs baseline: 1.1774x; 1.1774x over previous
#include <cuda_runtime.h>
#include <cuda_fp16.h>
#include <math.h>
#include <stdint.h>

#define BB   256
#define TT   256
#define DD   384
#define HH   64
#define MTOT (BB*TT)                       // 65536 rows
#define HEADELEMS ((size_t)MTOT*HH)

// scratch: q,k,v fp16 (attn operands) + transposed fp16 weights (proj)
__device__ __half g_h[3 * (size_t)MTOT * HH];
__device__ __half g_wh[192 * 384];

// ---------------------------------------------------------------------------
__device__ __forceinline__ uint32_t smem_u32(const void* p) {
    uint32_t a;
    asm("{ .reg .u64 t; cvta.to.shared.u64 t, %1; cvt.u32.u64 %0, t; }"
        : "=r"(a) : "l"(p));
    return a;
}

__device__ __forceinline__ void ldsm4(uint32_t r[4], uint32_t addr) {
    asm volatile("ldmatrix.sync.aligned.m8n8.x4.shared.b16 {%0,%1,%2,%3}, [%4];"
                 : "=r"(r[0]), "=r"(r[1]), "=r"(r[2]), "=r"(r[3]) : "r"(addr));
}

__device__ __forceinline__ void ldsm4t(uint32_t r[4], uint32_t addr) {
    asm volatile("ldmatrix.sync.aligned.m8n8.x4.trans.shared.b16 {%0,%1,%2,%3}, [%4];"
                 : "=r"(r[0]), "=r"(r[1]), "=r"(r[2]), "=r"(r[3]) : "r"(addr));
}

// fp16 mma
__device__ __forceinline__ void mma16816h(float c[4], const uint32_t a[4],
                                          uint32_t b0, uint32_t b1) {
    asm volatile(
        "mma.sync.aligned.m16n8k16.row.col.f32.f16.f16.f32 "
        "{%0,%1,%2,%3}, {%4,%5,%6,%7}, {%8,%9}, {%0,%1,%2,%3};"
        : "+f"(c[0]), "+f"(c[1]), "+f"(c[2]), "+f"(c[3])
        : "r"(a[0]), "r"(a[1]), "r"(a[2]), "r"(a[3]), "r"(b0), "r"(b1));
}

// pack two f32 -> f16x2 (first arg in low half)
__device__ __forceinline__ uint32_t packhf(float lo, float hi) {
    __half2 h = __floats2half2_rn(lo, hi);
    return *(uint32_t*)&h;
}

__device__ __forceinline__ void cpasync16(uint32_t dst, const void* src) {
    asm volatile("cp.async.cg.shared.global [%0], [%1], 16;"
                 :: "r"(dst), "l"(src));
}

// ---------------------------------------------------------------------------
// Weight prep: smem-tiled transpose, single fp16.
// ---------------------------------------------------------------------------
__global__ void wsplit_kernel(const float* __restrict__ Wq,
                              const float* __restrict__ Wk,
                              const float* __restrict__ Wv) {
    __shared__ float ws[32][65];
    const int sel = blockIdx.x / 12;
    const int k0  = (blockIdx.x % 12) * 32;
    const float* W = (sel == 0) ? Wq : (sel == 1) ? Wk : Wv;
    const int tid = threadIdx.x;

    #pragma unroll
    for (int it = 0; it < 8; ++it) {
        int idx = tid + it * 256;          // 0..2047
        int k = idx >> 6, n = idx & 63;
        ws[k][n] = W[(size_t)(k0 + k) * HH + n];
    }
    __syncthreads();
    #pragma unroll
    for (int it = 0; it < 8; ++it) {
        int idx = tid + it * 256;
        int n = idx >> 5, k = idx & 31;
        g_wh[(size_t)(sel * 64 + n) * DD + k0 + k] = __float2half_rn(ws[k][n]);
    }
}

// ---------------------------------------------------------------------------
// fp16 single-product projection, 512 threads (16 warps, 4m x 4n, warp tile
// 16x48), shallow 2-stage pipeline, 40KB smem -> 2 CTAs/SM = 32 warps/SM.
// ---------------------------------------------------------------------------
#define KC    32
#define KS    40
#define ABUFH 2560     // halves: 64*40 per stage (x2)
#define B_BASE 5120
#define BBUFH 7680     // halves: 192*40 per stage (x2)
#define PROJ_SMEM ((5120 + 15360) * 2)   // 40960 bytes

__global__ void __launch_bounds__(512, 2) proj_mma_kernel(const float* __restrict__ x)
{
    extern __shared__ __half sm[];
    const uint32_t sb = smem_u32(sm);
    const int tid  = threadIdx.x;
    const int lane = tid & 31;
    const int wid  = tid >> 5;       // 0..15
    const int wm   = wid >> 2;       // 4 m-blocks of 16 rows
    const int wn   = wid & 3;        // 4 n-blocks of 48 cols
    const int m0   = blockIdx.x * 64;

    const int aRow = lane & 15;                            // m within 16
    const int aCol = ((lane >> 4) & 1) * 8;                // k half
    const int bN   = (lane & 7) + ((lane >> 4) & 1) * 8;
    const int bK   = ((lane >> 3) & 1) * 8;

    float c[6][4];
    #pragma unroll
    for (int nt = 0; nt < 6; ++nt)
        #pragma unroll
        for (int j = 0; j < 4; ++j) c[nt][j] = 0.f;

    float4 aCur, aNxt;

    // per-thread A-load geometry: 512 float4s cover 64x32
    const int ar = tid >> 3;
    const int ac4 = (tid & 7) * 4;

    // ---- prologue: B(0) cp.async -> stage0, A(0) -> reg
    {
        #pragma unroll
        for (int it = 0; it < 2; ++it) {
            int idx = tid + it * 512;              // 0..1023; only <768 valid
            if (idx < 768) {
                int n  = idx >> 2;
                int kg = (idx & 3) * 8;
                cpasync16(sb + (uint32_t)(B_BASE + n * KS + kg) * 2,
                          g_wh + (size_t)n * DD + kg);
            }
        }
        asm volatile("cp.async.commit_group;" ::: "memory");
        aCur = *(const float4*)(x + (size_t)(m0 + ar) * DD + ac4);
    }

    #pragma unroll 1
    for (int ch = 0; ch < 12; ++ch) {
        // ---- STS A(ch) (convert fp32 -> fp16), one uint2 per thread
        {
            float4 v = aCur;
            int off = (ch & 1) * ABUFH + ar * KS + ac4;
            *(uint2*)(sm + off) = make_uint2(packhf(v.x, v.y), packhf(v.z, v.w));
        }

        // ---- drain B(ch), barrier
        asm volatile("cp.async.wait_group 0;" ::: "memory");
        __syncthreads();

        // ---- issue B(ch+1) + LDG A(ch+1); overlaps the MMA phase below
        if (ch < 11) {
            const int k1 = (ch + 1) * KC;
            #pragma unroll
            for (int it = 0; it < 2; ++it) {
                int idx = tid + it * 512;
                if (idx < 768) {
                    int n  = idx >> 2;
                    int kg = (idx & 3) * 8;
                    cpasync16(sb + (uint32_t)(B_BASE + ((ch + 1) & 1) * BBUFH +
                                              n * KS + kg) * 2,
                              g_wh + (size_t)n * DD + k1 + kg);
                }
            }
            asm volatile("cp.async.commit_group;" ::: "memory");
            aNxt = *(const float4*)(x + (size_t)(m0 + ar) * DD + k1 + ac4);
        }

        // ---- MMA over stage buffers
        const uint32_t aBase = (uint32_t)((ch & 1) * ABUFH);
        const uint32_t bBase = (uint32_t)(B_BASE + (ch & 1) * BBUFH);
        #pragma unroll
        for (int ks = 0; ks < 2; ++ks) {
            const int kk = ks * 16;
            uint32_t ah[4];
            {
                uint32_t off = (uint32_t)((wm * 16 + aRow) * KS + kk + aCol);
                ldsm4(ah, sb + (aBase + off) * 2);
            }
            #pragma unroll
            for (int np = 0; np < 3; ++np) {
                uint32_t boff = (uint32_t)((wn * 48 + np * 16 + bN) * KS + kk + bK);
                uint32_t bh[4];
                ldsm4(bh, sb + (bBase + boff) * 2);
                #pragma unroll
                for (int sub = 0; sub < 2; ++sub)
                    mma16816h(c[sub + np * 2], ah, bh[sub * 2], bh[sub * 2 + 1]);
            }
        }

        aCur = aNxt;
    }

    // ---- epilogue: fp32 acc -> single fp16 to g_h (q pre-scaled by 0.125)
    const int t4 = lane >> 2;
    const int c2 = (lane & 3) * 2;
    #pragma unroll
    for (int nt = 0; nt < 6; ++nt) {
        int col = wn * 48 + nt * 8 + c2;
        int sel = col >> 6;
        int hc  = col & 63;
        float s = (sel == 0) ? 0.125f : 1.0f;
        size_t base = (size_t)sel * HEADELEMS +
                      (size_t)(m0 + wm * 16 + t4) * HH + hc;
        *(uint32_t*)(g_h + base)          = packhf(c[nt][0] * s, c[nt][1] * s);
        *(uint32_t*)(g_h + base + 8 * HH) = packhf(c[nt][2] * s, c[nt][3] * s);
    }
}

// ---------------------------------------------------------------------------
// Tensor-core flash attention, fp16 single-product GEMMs, 2 CTAs/SM.
// (unchanged from R12)
// ---------------------------------------------------------------------------
#define AST 72
#define Q_S 0
#define K_S (256*AST)
#define V_S (2*256*AST)
#define ATTN_SMEM (3*256*AST*2)    // 110592 bytes

__global__ void __launch_bounds__(256, 2) attn_mma_kernel(float* __restrict__ out)
{
    extern __shared__ __half asmem[];
    const uint32_t sb = smem_u32(asmem);
    const int b    = blockIdx.x;
    const int tid  = threadIdx.x;
    const int lane = tid & 31;
    const int w    = tid >> 5;
    const int t4   = lane >> 2;
    const int tg   = lane & 3;

    // ---- cp.async load: 3 arrays of [256][64] fp16 -> stride-72 smem
    #pragma unroll
    for (int it = 0; it < 24; ++it) {
        const int arr = it >> 3;               // 8 iterations per array
        int rem = (tid + it * 256) - arr * 2048;
        int r   = rem >> 3;
        int kg  = (rem & 7) * 8;
        const __half* src = g_h + (size_t)arr * HEADELEMS +
                            ((size_t)b * TT + r) * HH + kg;
        uint32_t dst = sb + (uint32_t)(arr * 256 * AST + r * AST + kg) * 2;
        cpasync16(dst, src);
    }
    asm volatile("cp.async.commit_group;\n\tcp.async.wait_group 0;" ::: "memory");
    __syncthreads();

    const int Rb[2] = { 16 * w, 240 - 16 * w };

    float o[2][8][4];
    float mrow[2][2], lrow[2][2];
    #pragma unroll
    for (int mt = 0; mt < 2; ++mt) {
        mrow[mt][0] = mrow[mt][1] = -1e30f;
        lrow[mt][0] = lrow[mt][1] = 0.f;
        #pragma unroll
        for (int nt = 0; nt < 8; ++nt)
            #pragma unroll
            for (int j = 0; j < 4; ++j) o[mt][nt][j] = 0.f;
    }

    const int qRow = lane & 15;
    const int qCol = ((lane >> 4) & 1) * 8;
    const int kRow = (lane & 7) + ((lane >> 4) & 1) * 8;
    const int kCol = ((lane >> 3) & 1) * 8;
    const int vRow = lane & 15;
    const int vCol = ((lane >> 4) & 1) * 8;

    #pragma unroll 1
    for (int s0 = 0; s0 < TT; s0 += 64) {
        #pragma unroll
        for (int mt = 0; mt < 2; ++mt) {
            const int base = Rb[mt];
            if (s0 > base + 15) continue;

            const int npMax = min(4, ((base + 15 - s0) >> 4) + 1);

            // ---- S = Q K^T (fp16, single product)
            float sc[8][4];
            #pragma unroll
            for (int nt = 0; nt < 8; ++nt)
                #pragma unroll
                for (int j = 0; j < 4; ++j) sc[nt][j] = 0.f;

            #pragma unroll
            for (int kc = 0; kc < 4; ++kc) {
                uint32_t qh[4];
                uint32_t qoff = (uint32_t)((base + qRow) * AST + kc * 16 + qCol);
                ldsm4(qh, sb + (Q_S + qoff) * 2);
                #pragma unroll
                for (int np = 0; np < 4; ++np) {
                    if (np < npMax) {
                        uint32_t koff = (uint32_t)((s0 + np * 16 + kRow) * AST + kc * 16 + kCol);
                        uint32_t kh[4];
                        ldsm4(kh, sb + (K_S + koff) * 2);
                        mma16816h(sc[2 * np],     qh, kh[0], kh[1]);
                        mma16816h(sc[2 * np + 1], qh, kh[2], kh[3]);
                    }
                }
            }

            // ---- causal mask + online softmax
            const int r0 = base + t4;
            const int r1 = r0 + 8;
            #pragma unroll
            for (int nt = 0; nt < 8; ++nt) {
                int col = s0 + 8 * nt + 2 * tg;
                if (col     > r0) sc[nt][0] = -1e30f;
                if (col + 1 > r0) sc[nt][1] = -1e30f;
                if (col     > r1) sc[nt][2] = -1e30f;
                if (col + 1 > r1) sc[nt][3] = -1e30f;
            }
            float mx0 = sc[0][0], mx1 = sc[0][2];
            #pragma unroll
            for (int nt = 0; nt < 8; ++nt) {
                mx0 = fmaxf(mx0, fmaxf(sc[nt][0], sc[nt][1]));
                mx1 = fmaxf(mx1, fmaxf(sc[nt][2], sc[nt][3]));
            }
            mx0 = fmaxf(mx0, __shfl_xor_sync(0xffffffffu, mx0, 1));
            mx0 = fmaxf(mx0, __shfl_xor_sync(0xffffffffu, mx0, 2));
            mx1 = fmaxf(mx1, __shfl_xor_sync(0xffffffffu, mx1, 1));
            mx1 = fmaxf(mx1, __shfl_xor_sync(0xffffffffu, mx1, 2));

            float nm0 = fmaxf(mrow[mt][0], mx0);
            float nm1 = fmaxf(mrow[mt][1], mx1);
            float corr0 = __expf(mrow[mt][0] - nm0);
            float corr1 = __expf(mrow[mt][1] - nm1);
            mrow[mt][0] = nm0;
            mrow[mt][1] = nm1;

            float sum0 = 0.f, sum1 = 0.f;
            #pragma unroll
            for (int nt = 0; nt < 8; ++nt) {
                sc[nt][0] = __expf(sc[nt][0] - nm0);
                sc[nt][1] = __expf(sc[nt][1] - nm0);
                sc[nt][2] = __expf(sc[nt][2] - nm1);
                sc[nt][3] = __expf(sc[nt][3] - nm1);
                sum0 += sc[nt][0] + sc[nt][1];
                sum1 += sc[nt][2] + sc[nt][3];
            }
            sum0 += __shfl_xor_sync(0xffffffffu, sum0, 1);
            sum0 += __shfl_xor_sync(0xffffffffu, sum0, 2);
            sum1 += __shfl_xor_sync(0xffffffffu, sum1, 1);
            sum1 += __shfl_xor_sync(0xffffffffu, sum1, 2);
            lrow[mt][0] = lrow[mt][0] * corr0 + sum0;
            lrow[mt][1] = lrow[mt][1] * corr1 + sum1;

            #pragma unroll
            for (int nt = 0; nt < 8; ++nt) {
                o[mt][nt][0] *= corr0;
                o[mt][nt][1] *= corr0;
                o[mt][nt][2] *= corr1;
                o[mt][nt][3] *= corr1;
            }

            // ---- O += P V (fp16, single product); skip zero tiles
            #pragma unroll
            for (int kv = 0; kv < 4; ++kv) {
                if (kv < npMax) {
                    uint32_t ph[4];
                    #pragma unroll
                    for (int half = 0; half < 2; ++half) {
                        const float* f = sc[2 * kv + half];
                        ph[2 * half]     = packhf(f[0], f[1]);
                        ph[2 * half + 1] = packhf(f[2], f[3]);
                    }
                    #pragma unroll
                    for (int np = 0; np < 4; ++np) {
                        uint32_t voff = (uint32_t)((s0 + kv * 16 + vRow) * AST + np * 16 + vCol);
                        uint32_t vh[4];
                        ldsm4t(vh, sb + (V_S + voff) * 2);
                        mma16816h(o[mt][2 * np],     ph, vh[0], vh[1]);
                        mma16816h(o[mt][2 * np + 1], ph, vh[2], vh[3]);
                    }
                }
            }
        }
    }

    // ---- write out
    #pragma unroll
    for (int mt = 0; mt < 2; ++mt) {
        const int r0 = Rb[mt] + t4;
        const float inv0 = 1.f / lrow[mt][0];
        const float inv1 = 1.f / lrow[mt][1];
        #pragma unroll
        for (int nt = 0; nt < 8; ++nt) {
            int col = 8 * nt + 2 * tg;
            size_t o0 = ((size_t)b * TT + r0) * HH + col;
            *(float2*)(out + o0)           = make_float2(o[mt][nt][0] * inv0,
                                                         o[mt][nt][1] * inv0);
            *(float2*)(out + o0 + 8 * HH)  = make_float2(o[mt][nt][2] * inv1,
                                                         o[mt][nt][3] * inv1);
        }
    }
}

// ---------------------------------------------------------------------------
extern "C" void kernel_launch(void* const* d_in, const int* in_sizes, int n_in,
                              void* d_out, int out_size)
{
    const float* x  = (const float*)d_in[0];
    const float* Wq = (const float*)d_in[1];
    const float* Wk = (const float*)d_in[2];
    const float* Wv = (const float*)d_in[3];
    float* out = (float*)d_out;

    cudaFuncSetAttribute(proj_mma_kernel,
                         cudaFuncAttributeMaxDynamicSharedMemorySize, PROJ_SMEM);
    cudaFuncSetAttribute(attn_mma_kernel,
                         cudaFuncAttributeMaxDynamicSharedMemorySize, ATTN_SMEM);

    wsplit_kernel<<<36, 256>>>(Wq, Wk, Wv);
    proj_mma_kernel<<<MTOT / 64, 512, PROJ_SMEM>>>(x);
    attn_mma_kernel<<<BB, 256, ATTN_SMEM>>>(out);
}

// round 17
// speedup vs baseline: 1.2037x; 1.0224x over previous
#include <cuda_runtime.h>
#include <cuda_fp16.h>
#include <math.h>
#include <stdint.h>

#define BB   256
#define TT   256
#define DD   384
#define HH   64
#define MTOT (BB*TT)                       // 65536 rows
#define HEADELEMS ((size_t)MTOT*HH)

// scratch: q,k,v fp16 (attn operands) + transposed fp16 weights (proj)
__device__ __half g_h[3 * (size_t)MTOT * HH];
__device__ __half g_wh[192 * 384];

// ---------------------------------------------------------------------------
__device__ __forceinline__ uint32_t smem_u32(const void* p) {
    uint32_t a;
    asm("{ .reg .u64 t; cvta.to.shared.u64 t, %1; cvt.u32.u64 %0, t; }"
        : "=r"(a) : "l"(p));
    return a;
}

__device__ __forceinline__ void ldsm4(uint32_t r[4], uint32_t addr) {
    asm volatile("ldmatrix.sync.aligned.m8n8.x4.shared.b16 {%0,%1,%2,%3}, [%4];"
                 : "=r"(r[0]), "=r"(r[1]), "=r"(r[2]), "=r"(r[3]) : "r"(addr));
}

__device__ __forceinline__ void ldsm4t(uint32_t r[4], uint32_t addr) {
    asm volatile("ldmatrix.sync.aligned.m8n8.x4.trans.shared.b16 {%0,%1,%2,%3}, [%4];"
                 : "=r"(r[0]), "=r"(r[1]), "=r"(r[2]), "=r"(r[3]) : "r"(addr));
}

// fp16 mma
__device__ __forceinline__ void mma16816h(float c[4], const uint32_t a[4],
                                          uint32_t b0, uint32_t b1) {
    asm volatile(
        "mma.sync.aligned.m16n8k16.row.col.f32.f16.f16.f32 "
        "{%0,%1,%2,%3}, {%4,%5,%6,%7}, {%8,%9}, {%0,%1,%2,%3};"
        : "+f"(c[0]), "+f"(c[1]), "+f"(c[2]), "+f"(c[3])
        : "r"(a[0]), "r"(a[1]), "r"(a[2]), "r"(a[3]), "r"(b0), "r"(b1));
}

// pack two f32 -> f16x2 (first arg in low half)
__device__ __forceinline__ uint32_t packhf(float lo, float hi) {
    __half2 h = __floats2half2_rn(lo, hi);
    return *(uint32_t*)&h;
}

__device__ __forceinline__ void cpasync16(uint32_t dst, const void* src) {
    asm volatile("cp.async.cg.shared.global [%0], [%1], 16;"
                 :: "r"(dst), "l"(src));
}

// ---------------------------------------------------------------------------
// Weight prep: smem-tiled transpose, single fp16.
// ---------------------------------------------------------------------------
__global__ void wsplit_kernel(const float* __restrict__ Wq,
                              const float* __restrict__ Wk,
                              const float* __restrict__ Wv) {
    __shared__ float ws[32][65];
    const int sel = blockIdx.x / 12;
    const int k0  = (blockIdx.x % 12) * 32;
    const float* W = (sel == 0) ? Wq : (sel == 1) ? Wk : Wv;
    const int tid = threadIdx.x;

    #pragma unroll
    for (int it = 0; it < 8; ++it) {
        int idx = tid + it * 256;          // 0..2047
        int k = idx >> 6, n = idx & 63;
        ws[k][n] = W[(size_t)(k0 + k) * HH + n];
    }
    __syncthreads();
    #pragma unroll
    for (int it = 0; it < 8; ++it) {
        int idx = tid + it * 256;
        int n = idx >> 5, k = idx & 31;
        g_wh[(size_t)(sel * 64 + n) * DD + k0 + k] = __float2half_rn(ws[k][n]);
    }
}

// ---------------------------------------------------------------------------
// fp16 single-product projection, M-tile 128, 512 threads (16 warps 4m x 4n,
// warp tile 32x48). 4-stage B cp.async ring (wait_group 2), A LDG 2 ahead.
// Halves total B traffic + per-CTA overheads vs M=64.
// ---------------------------------------------------------------------------
#define KC    32
#define KS    40
#define ABUFH 5120     // halves: 128*40 per A stage (x2)
#define B_BASE 10240   // halves
#define BBUFH 7680     // halves: 192*40 per B stage (x4)
#define PROJ_SMEM ((10240 + 4 * 7680) * 2)   // 81920 bytes

__global__ void __launch_bounds__(512, 1) proj_mma_kernel(const float* __restrict__ x)
{
    extern __shared__ __half sm[];
    const uint32_t sb = smem_u32(sm);
    const int tid  = threadIdx.x;
    const int lane = tid & 31;
    const int wid  = tid >> 5;       // 0..15
    const int wm   = wid >> 2;       // 4 m-blocks of 32 rows
    const int wn   = wid & 3;        // 4 n-blocks of 48 cols
    const int m0   = blockIdx.x * 128;

    const int aRow = (lane & 7) + ((lane >> 3) & 1) * 8;
    const int aCol = ((lane >> 4) & 1) * 8;
    const int bN   = (lane & 7) + ((lane >> 4) & 1) * 8;
    const int bK   = ((lane >> 3) & 1) * 8;

    float c[2][6][4];
    #pragma unroll
    for (int mt = 0; mt < 2; ++mt)
        #pragma unroll
        for (int nt = 0; nt < 6; ++nt)
            #pragma unroll
            for (int j = 0; j < 4; ++j) c[mt][nt][j] = 0.f;

    float4 a0[2], a1[2], a2[2];

    // per-thread A-load geometry: 1024 float4s cover 128x32
    // it in {0,1}: idx = tid + it*512, r = idx>>3 (0..127), c4 = (idx&7)*4

    // ---- prologue: B(0), B(1) cp.async (groups 0,1); A(0), A(1) LDG
    #pragma unroll
    for (int s = 0; s < 2; ++s) {
        #pragma unroll
        for (int it = 0; it < 2; ++it) {
            int idx = tid + it * 512;              // 0..1023, guard < 768
            if (idx < 768) {
                int n  = idx >> 2;
                int kg = (idx & 3) * 8;
                cpasync16(sb + (uint32_t)(B_BASE + s * BBUFH + n * KS + kg) * 2,
                          g_wh + (size_t)n * DD + s * KC + kg);
            }
        }
        asm volatile("cp.async.commit_group;" ::: "memory");
    }
    #pragma unroll
    for (int it = 0; it < 2; ++it) {
        int idx = tid + it * 512;
        int r = idx >> 3, c4 = (idx & 7) * 4;
        a0[it] = *(const float4*)(x + (size_t)(m0 + r) * DD + c4);
        a1[it] = *(const float4*)(x + (size_t)(m0 + r) * DD + KC + c4);
    }

    #pragma unroll 1
    for (int ch = 0; ch < 12; ++ch) {
        // ---- issue B(ch+2) + LDG A(ch+2) (2 chunks ahead)
        if (ch < 10) {
            const int k2 = (ch + 2) * KC;
            #pragma unroll
            for (int it = 0; it < 2; ++it) {
                int idx = tid + it * 512;
                if (idx < 768) {
                    int n  = idx >> 2;
                    int kg = (idx & 3) * 8;
                    cpasync16(sb + (uint32_t)(B_BASE + ((ch + 2) & 3) * BBUFH +
                                              n * KS + kg) * 2,
                              g_wh + (size_t)n * DD + k2 + kg);
                }
            }
            asm volatile("cp.async.commit_group;" ::: "memory");
            #pragma unroll
            for (int it = 0; it < 2; ++it) {
                int idx = tid + it * 512;
                int r = idx >> 3, c4 = (idx & 7) * 4;
                a2[it] = *(const float4*)(x + (size_t)(m0 + r) * DD + k2 + c4);
            }
        } else {
            asm volatile("cp.async.commit_group;" ::: "memory");   // empty group
        }

        // ---- STS A(ch) (convert fp32 -> fp16)
        #pragma unroll
        for (int it = 0; it < 2; ++it) {
            int idx = tid + it * 512;
            int r = idx >> 3, c4 = (idx & 7) * 4;
            float4 v = a0[it];
            int off = (ch & 1) * ABUFH + r * KS + c4;
            *(uint2*)(sm + off) = make_uint2(packhf(v.x, v.y), packhf(v.z, v.w));
        }

        // ---- B(ch) guaranteed complete with 2 groups still in flight
        asm volatile("cp.async.wait_group 2;" ::: "memory");
        __syncthreads();

        // ---- MMA over stage buffers
        const uint32_t aBase = (uint32_t)((ch & 1) * ABUFH);
        const uint32_t bBase = (uint32_t)(B_BASE + (ch & 3) * BBUFH);
        #pragma unroll
        for (int ks = 0; ks < 2; ++ks) {
            const int kk = ks * 16;
            uint32_t ah[2][4];
            #pragma unroll
            for (int mt = 0; mt < 2; ++mt) {
                uint32_t off = (uint32_t)((wm * 32 + mt * 16 + aRow) * KS + kk + aCol);
                ldsm4(ah[mt], sb + (aBase + off) * 2);
            }
            #pragma unroll
            for (int np = 0; np < 3; ++np) {
                uint32_t boff = (uint32_t)((wn * 48 + np * 16 + bN) * KS + kk + bK);
                uint32_t bh[4];
                ldsm4(bh, sb + (bBase + boff) * 2);
                #pragma unroll
                for (int mt = 0; mt < 2; ++mt)
                    #pragma unroll
                    for (int sub = 0; sub < 2; ++sub)
                        mma16816h(c[mt][sub + np * 2], ah[mt],
                                  bh[sub * 2], bh[sub * 2 + 1]);
            }
        }

        a0[0] = a1[0]; a0[1] = a1[1];
        a1[0] = a2[0]; a1[1] = a2[1];
    }

    // ---- epilogue: fp32 acc -> single fp16 to g_h (q pre-scaled by 0.125)
    const int t4 = lane >> 2;
    const int c2 = (lane & 3) * 2;
    #pragma unroll
    for (int mt = 0; mt < 2; ++mt)
        #pragma unroll
        for (int nt = 0; nt < 6; ++nt) {
            int col = wn * 48 + nt * 8 + c2;
            int sel = col >> 6;
            int hc  = col & 63;
            float s = (sel == 0) ? 0.125f : 1.0f;
            size_t base = (size_t)sel * HEADELEMS +
                          (size_t)(m0 + wm * 32 + mt * 16 + t4) * HH + hc;
            *(uint32_t*)(g_h + base) =
                packhf(c[mt][nt][0] * s, c[mt][nt][1] * s);
            *(uint32_t*)(g_h + base + 8 * HH) =
                packhf(c[mt][nt][2] * s, c[mt][nt][3] * s);
        }
}

// ---------------------------------------------------------------------------
// Tensor-core flash attention, fp16 single-product GEMMs, 2 CTAs/SM.
// (unchanged from R12)
// ---------------------------------------------------------------------------
#define AST 72
#define Q_S 0
#define K_S (256*AST)
#define V_S (2*256*AST)
#define ATTN_SMEM (3*256*AST*2)    // 110592 bytes

__global__ void __launch_bounds__(256, 2) attn_mma_kernel(float* __restrict__ out)
{
    extern __shared__ __half asmem[];
    const uint32_t sb = smem_u32(asmem);
    const int b    = blockIdx.x;
    const int tid  = threadIdx.x;
    const int lane = tid & 31;
    const int w    = tid >> 5;
    const int t4   = lane >> 2;
    const int tg   = lane & 3;

    // ---- cp.async load: 3 arrays of [256][64] fp16 -> stride-72 smem
    #pragma unroll
    for (int it = 0; it < 24; ++it) {
        const int arr = it >> 3;               // 8 iterations per array
        int rem = (tid + it * 256) - arr * 2048;
        int r   = rem >> 3;
        int kg  = (rem & 7) * 8;
        const __half* src = g_h + (size_t)arr * HEADELEMS +
                            ((size_t)b * TT + r) * HH + kg;
        uint32_t dst = sb + (uint32_t)(arr * 256 * AST + r * AST + kg) * 2;
        cpasync16(dst, src);
    }
    asm volatile("cp.async.commit_group;\n\tcp.async.wait_group 0;" ::: "memory");
    __syncthreads();

    const int Rb[2] = { 16 * w, 240 - 16 * w };

    float o[2][8][4];
    float mrow[2][2], lrow[2][2];
    #pragma unroll
    for (int mt = 0; mt < 2; ++mt) {
        mrow[mt][0] = mrow[mt][1] = -1e30f;
        lrow[mt][0] = lrow[mt][1] = 0.f;
        #pragma unroll
        for (int nt = 0; nt < 8; ++nt)
            #pragma unroll
            for (int j = 0; j < 4; ++j) o[mt][nt][j] = 0.f;
    }

    const int qRow = lane & 15;
    const int qCol = ((lane >> 4) & 1) * 8;
    const int kRow = (lane & 7) + ((lane >> 4) & 1) * 8;
    const int kCol = ((lane >> 3) & 1) * 8;
    const int vRow = lane & 15;
    const int vCol = ((lane >> 4) & 1) * 8;

    #pragma unroll 1
    for (int s0 = 0; s0 < TT; s0 += 64) {
        #pragma unroll
        for (int mt = 0; mt < 2; ++mt) {
            const int base = Rb[mt];
            if (s0 > base + 15) continue;

            const int npMax = min(4, ((base + 15 - s0) >> 4) + 1);

            // ---- S = Q K^T (fp16, single product)
            float sc[8][4];
            #pragma unroll
            for (int nt = 0; nt < 8; ++nt)
                #pragma unroll
                for (int j = 0; j < 4; ++j) sc[nt][j] = 0.f;

            #pragma unroll
            for (int kc = 0; kc < 4; ++kc) {
                uint32_t qh[4];
                uint32_t qoff = (uint32_t)((base + qRow) * AST + kc * 16 + qCol);
                ldsm4(qh, sb + (Q_S + qoff) * 2);
                #pragma unroll
                for (int np = 0; np < 4; ++np) {
                    if (np < npMax) {
                        uint32_t koff = (uint32_t)((s0 + np * 16 + kRow) * AST + kc * 16 + kCol);
                        uint32_t kh[4];
                        ldsm4(kh, sb + (K_S + koff) * 2);
                        mma16816h(sc[2 * np],     qh, kh[0], kh[1]);
                        mma16816h(sc[2 * np + 1], qh, kh[2], kh[3]);
                    }
                }
            }

            // ---- causal mask + online softmax
            const int r0 = base + t4;
            const int r1 = r0 + 8;
            #pragma unroll
            for (int nt = 0; nt < 8; ++nt) {
                int col = s0 + 8 * nt + 2 * tg;
                if (col     > r0) sc[nt][0] = -1e30f;
                if (col + 1 > r0) sc[nt][1] = -1e30f;
                if (col     > r1) sc[nt][2] = -1e30f;
                if (col + 1 > r1) sc[nt][3] = -1e30f;
            }
            float mx0 = sc[0][0], mx1 = sc[0][2];
            #pragma unroll
            for (int nt = 0; nt < 8; ++nt) {
                mx0 = fmaxf(mx0, fmaxf(sc[nt][0], sc[nt][1]));
                mx1 = fmaxf(mx1, fmaxf(sc[nt][2], sc[nt][3]));
            }
            mx0 = fmaxf(mx0, __shfl_xor_sync(0xffffffffu, mx0, 1));
            mx0 = fmaxf(mx0, __shfl_xor_sync(0xffffffffu, mx0, 2));
            mx1 = fmaxf(mx1, __shfl_xor_sync(0xffffffffu, mx1, 1));
            mx1 = fmaxf(mx1, __shfl_xor_sync(0xffffffffu, mx1, 2));

            float nm0 = fmaxf(mrow[mt][0], mx0);
            float nm1 = fmaxf(mrow[mt][1], mx1);
            float corr0 = __expf(mrow[mt][0] - nm0);
            float corr1 = __expf(mrow[mt][1] - nm1);
            mrow[mt][0] = nm0;
            mrow[mt][1] = nm1;

            float sum0 = 0.f, sum1 = 0.f;
            #pragma unroll
            for (int nt = 0; nt < 8; ++nt) {
                sc[nt][0] = __expf(sc[nt][0] - nm0);
                sc[nt][1] = __expf(sc[nt][1] - nm0);
                sc[nt][2] = __expf(sc[nt][2] - nm1);
                sc[nt][3] = __expf(sc[nt][3] - nm1);
                sum0 += sc[nt][0] + sc[nt][1];
                sum1 += sc[nt][2] + sc[nt][3];
            }
            sum0 += __shfl_xor_sync(0xffffffffu, sum0, 1);
            sum0 += __shfl_xor_sync(0xffffffffu, sum0, 2);
            sum1 += __shfl_xor_sync(0xffffffffu, sum1, 1);
            sum1 += __shfl_xor_sync(0xffffffffu, sum1, 2);
            lrow[mt][0] = lrow[mt][0] * corr0 + sum0;
            lrow[mt][1] = lrow[mt][1] * corr1 + sum1;

            #pragma unroll
            for (int nt = 0; nt < 8; ++nt) {
                o[mt][nt][0] *= corr0;
                o[mt][nt][1] *= corr0;
                o[mt][nt][2] *= corr1;
                o[mt][nt][3] *= corr1;
            }

            // ---- O += P V (fp16, single product); skip zero tiles
            #pragma unroll
            for (int kv = 0; kv < 4; ++kv) {
                if (kv < npMax) {
                    uint32_t ph[4];
                    #pragma unroll
                    for (int half = 0; half < 2; ++half) {
                        const float* f = sc[2 * kv + half];
                        ph[2 * half]     = packhf(f[0], f[1]);
                        ph[2 * half + 1] = packhf(f[2], f[3]);
                    }
                    #pragma unroll
                    for (int np = 0; np < 4; ++np) {
                        uint32_t voff = (uint32_t)((s0 + kv * 16 + vRow) * AST + np * 16 + vCol);
                        uint32_t vh[4];
                        ldsm4t(vh, sb + (V_S + voff) * 2);
                        mma16816h(o[mt][2 * np],     ph, vh[0], vh[1]);
                        mma16816h(o[mt][2 * np + 1], ph, vh[2], vh[3]);
                    }
                }
            }
        }
    }

    // ---- write out
    #pragma unroll
    for (int mt = 0; mt < 2; ++mt) {
        const int r0 = Rb[mt] + t4;
        const float inv0 = 1.f / lrow[mt][0];
        const float inv1 = 1.f / lrow[mt][1];
        #pragma unroll
        for (int nt = 0; nt < 8; ++nt) {
            int col = 8 * nt + 2 * tg;
            size_t o0 = ((size_t)b * TT + r0) * HH + col;
            *(float2*)(out + o0)           = make_float2(o[mt][nt][0] * inv0,
                                                         o[mt][nt][1] * inv0);
            *(float2*)(out + o0 + 8 * HH)  = make_float2(o[mt][nt][2] * inv1,
                                                         o[mt][nt][3] * inv1);
        }
    }
}

// ---------------------------------------------------------------------------
extern "C" void kernel_launch(void* const* d_in, const int* in_sizes, int n_in,
                              void* d_out, int out_size)
{
    const float* x  = (const float*)d_in[0];
    const float* Wq = (const float*)d_in[1];
    const float* Wk = (const float*)d_in[2];
    const float* Wv = (const float*)d_in[3];
    float* out = (float*)d_out;

    cudaFuncSetAttribute(proj_mma_kernel,
                         cudaFuncAttributeMaxDynamicSharedMemorySize, PROJ_SMEM);
    cudaFuncSetAttribute(attn_mma_kernel,
                         cudaFuncAttributeMaxDynamicSharedMemorySize, ATTN_SMEM);

    wsplit_kernel<<<36, 256>>>(Wq, Wk, Wv);
    proj_mma_kernel<<<MTOT / 128, 512, PROJ_SMEM>>>(x);
    attn_mma_kernel<<<BB, 256, ATTN_SMEM>>>(out);
}